// round 7
// baseline (speedup 1.0000x reference)
#include <cuda_runtime.h>
#include <math.h>

#define D_HALF   512
#define NPOS     8192
#define SPINE_N  10
#define MAX_TOK  131072
#define CAP      64          // bucket capacity per position (mean load 16)

__constant__ int c_spine[SPINE_N] = {0, 2, 4, 12, 36, 104, 304, 888, 2592, 7568};

// Bucketing scratch (device globals: no allocation allowed).
__device__ int g_cursor[NPOS];            // memset 0 each call
__device__ int g_bucket[NPOS * CAP];      // 2 MiB
__device__ int g_ovf_head[NPOS];          // memset -1 each call (overflow lists)
__device__ int g_ovf_next[MAX_TOK];

// Single pass: drop each token into its position's bucket (overflow -> list).
__global__ void __launch_bounds__(256) scatter_kernel(
    const int* __restrict__ positions, int ntok)
{
    const int i = blockIdx.x * blockDim.x + threadIdx.x;
    if (i < ntok) {
        const int pos  = positions[i];
        const int slot = atomicAdd(&g_cursor[pos], 1);
        if (slot < CAP) {
            g_bucket[pos * CAP + slot] = i;
        } else {
            g_ovf_next[i] = atomicExch(&g_ovf_head[pos], i);
        }
    }
}

// One block per position: compute lat-enc row ONCE in registers
// (Linear(3,512) -> LayerNorm -> exact GELU), load pe row once, pull the
// bucket into smem in ONE parallel burst, then pure-store streaming loop.
__global__ void __launch_bounds__(128) gather_kernel(
    const float4* __restrict__ pe4,    // [NPOS, 128] float4
    const float*  __restrict__ W1,     // [512, 3] row-major
    const float*  __restrict__ b1,
    const float*  __restrict__ gamma,
    const float*  __restrict__ beta,
    float4*       __restrict__ out4)   // [ntok, 256] float4
{
    const int pos = blockIdx.x;
    const int tid = threadIdx.x;       // 128 threads, dims 4*tid..4*tid+3

    __shared__ int stok[CAP];
    __shared__ float sred[4];

    const int total = g_cursor[pos];   // broadcast
    if (total == 0) return;
    const int cnt = (total < CAP) ? total : CAP;

    // Parallel bucket fetch: independent coalesced loads, no chase.
    if (tid < cnt) stok[tid] = g_bucket[pos * CAP + tid];

    // --- lattice features (scalar, per block) ---
    int level = 0;
#pragma unroll
    for (int i = 0; i < SPINE_N; i++) level += (c_spine[i] <= pos) ? 1 : 0;
    const float left  = (float)(pos - c_spine[level - 1]);
    const float right = (level < SPINE_N) ? (float)(c_spine[level] - pos) : 0.0f;
    const float lv    = (float)level;

    // --- h = feats @ W1^T + b1, dims 4*tid..4*tid+3 ---
    float h[4];
    float lsum = 0.0f;
#pragma unroll
    for (int k = 0; k < 4; k++) {
        const int d = 4 * tid + k;
        h[k] = fmaf(__ldg(&W1[d * 3 + 0]), left,
               fmaf(__ldg(&W1[d * 3 + 1]), right,
               fmaf(__ldg(&W1[d * 3 + 2]), lv, __ldg(&b1[d]))));
        lsum += h[k];
    }

    // --- block LayerNorm (mean, then two-pass variance) ---
#pragma unroll
    for (int o = 16; o > 0; o >>= 1) lsum += __shfl_xor_sync(0xffffffffu, lsum, o);
    if ((tid & 31) == 0) sred[tid >> 5] = lsum;
    __syncthreads();
    const float mu = (sred[0] + sred[1] + sred[2] + sred[3]) * (1.0f / (float)D_HALF);

    float vs = 0.0f;
#pragma unroll
    for (int k = 0; k < 4; k++) { const float dd = h[k] - mu; vs = fmaf(dd, dd, vs); }
    __syncthreads();
#pragma unroll
    for (int o = 16; o > 0; o >>= 1) vs += __shfl_xor_sync(0xffffffffu, vs, o);
    if ((tid & 31) == 0) sred[tid >> 5] = vs;
    __syncthreads();
    const float rstd = rsqrtf((sred[0] + sred[1] + sred[2] + sred[3]) *
                              (1.0f / (float)D_HALF) + 1e-5f);

    // --- gamma/beta + exact-erf GELU, packed as float4 ---
    float4 lat;
    {
        float g[4];
#pragma unroll
        for (int k = 0; k < 4; k++) {
            const int d = 4 * tid + k;
            const float x = fmaf((h[k] - mu) * rstd, __ldg(&gamma[d]), __ldg(&beta[d]));
            g[k] = 0.5f * x * (1.0f + erff(x * 0.70710678118654752440f));
        }
        lat = make_float4(g[0], g[1], g[2], g[3]);
    }

    // --- pe row (read once per position) ---
    const float4 pev = __ldg(&pe4[(size_t)pos * 128 + tid]);

    __syncthreads();  // stok visible

    // --- pure streaming-store loop over this position's tokens (avg ~16) ---
    for (int j = 0; j < cnt; j++) {
        float4* __restrict__ dst = out4 + (size_t)stok[j] * 256;
        __stcs(dst + tid,       pev);
        __stcs(dst + 128 + tid, lat);
    }

    // --- overflow list (expected empty; correctness safety net) ---
    if (total > CAP) {
        int tok = g_ovf_head[pos];
        while (tok >= 0) {
            float4* __restrict__ dst = out4 + (size_t)tok * 256;
            __stcs(dst + tid,       pev);
            __stcs(dst + 128 + tid, lat);
            tok = g_ovf_next[tok];
        }
    }
}

extern "C" void kernel_launch(void* const* d_in, const int* in_sizes, int n_in,
                              void* d_out, int out_size)
{
    const int*   positions = (const int*)  d_in[0];
    const float* pe        = (const float*)d_in[1];
    const float* W1        = (const float*)d_in[2];
    const float* b1        = (const float*)d_in[3];
    const float* ln_gamma  = (const float*)d_in[4];
    const float* ln_beta   = (const float*)d_in[5];
    float* out = (float*)d_out;

    const int ntok = in_sizes[0];  // B*S = 131072

    void* cur_ptr = nullptr; cudaGetSymbolAddress(&cur_ptr, g_cursor);
    void* ovf_ptr = nullptr; cudaGetSymbolAddress(&ovf_ptr, g_ovf_head);
    cudaMemsetAsync(cur_ptr, 0x00, NPOS * sizeof(int));
    cudaMemsetAsync(ovf_ptr, 0xFF, NPOS * sizeof(int));

    scatter_kernel<<<(ntok + 255) / 256, 256>>>(positions, ntok);

    gather_kernel<<<NPOS, 128>>>((const float4*)pe, W1, b1, ln_gamma, ln_beta,
                                 (float4*)out);
}

// round 8
// speedup vs baseline: 1.2710x; 1.2710x over previous
#include <cuda_runtime.h>
#include <math.h>
#include <stdint.h>

#define D_HALF   512
#define NPOS     8192
#define SPINE_N  10
#define MAX_TOK  131072

__constant__ int c_spine[SPINE_N] = {0, 2, 4, 12, 36, 104, 304, 888, 2592, 7568};

// Per-position token linked lists (device globals: no allocation allowed).
__device__ int g_head[NPOS];     // memset to -1 each call
__device__ int g_next[MAX_TOK];

// Single pass: push each token onto its position's list.
__global__ void __launch_bounds__(256) build_kernel(
    const int* __restrict__ positions, int ntok)
{
    const int i = blockIdx.x * blockDim.x + threadIdx.x;
    if (i < ntok) {
        const int pos = positions[i];
        g_next[i] = atomicExch(&g_head[pos], i);
    }
}

// One block per position: build the 4 KB concat row (pe || GELU(LN(W1·feats)))
// ONCE in shared memory, then replay it to every token's output row using
// cp.async.bulk (TMA/DMA engine) — the SM issues ~16 instructions instead of
// ~4096 lane stores, removing the LSU store-feed bottleneck.
__global__ void __launch_bounds__(128) gather_kernel(
    const float4* __restrict__ pe4,    // [NPOS, 128] float4
    const float*  __restrict__ W1,     // [512, 3] row-major
    const float*  __restrict__ b1,
    const float*  __restrict__ gamma,
    const float*  __restrict__ beta,
    float4*       __restrict__ out4)   // [ntok, 256] float4
{
    __shared__ alignas(128) float4 srow[256];  // 4 KB: [0,128)=pe, [128,256)=lat
    __shared__ float sred[4];

    const int pos = blockIdx.x;
    const int tid = threadIdx.x;       // 128 threads, dims 4*tid..4*tid+3

    const int head = g_head[pos];      // block-uniform broadcast
    if (head < 0) return;              // no tokens with this position

    // --- lattice features (scalar, per block) ---
    int level = 0;
#pragma unroll
    for (int i = 0; i < SPINE_N; i++) level += (c_spine[i] <= pos) ? 1 : 0;
    const float left  = (float)(pos - c_spine[level - 1]);
    const float right = (level < SPINE_N) ? (float)(c_spine[level] - pos) : 0.0f;
    const float lv    = (float)level;

    // --- h = feats @ W1^T + b1, dims 4*tid..4*tid+3 ---
    float h[4];
    float lsum = 0.0f;
#pragma unroll
    for (int k = 0; k < 4; k++) {
        const int d = 4 * tid + k;
        h[k] = fmaf(__ldg(&W1[d * 3 + 0]), left,
               fmaf(__ldg(&W1[d * 3 + 1]), right,
               fmaf(__ldg(&W1[d * 3 + 2]), lv, __ldg(&b1[d]))));
        lsum += h[k];
    }

    // --- block LayerNorm (mean, then two-pass variance) ---
#pragma unroll
    for (int o = 16; o > 0; o >>= 1) lsum += __shfl_xor_sync(0xffffffffu, lsum, o);
    if ((tid & 31) == 0) sred[tid >> 5] = lsum;
    __syncthreads();
    const float mu = (sred[0] + sred[1] + sred[2] + sred[3]) * (1.0f / (float)D_HALF);

    float vs = 0.0f;
#pragma unroll
    for (int k = 0; k < 4; k++) { const float dd = h[k] - mu; vs = fmaf(dd, dd, vs); }
    __syncthreads();
#pragma unroll
    for (int o = 16; o > 0; o >>= 1) vs += __shfl_xor_sync(0xffffffffu, vs, o);
    if ((tid & 31) == 0) sred[tid >> 5] = vs;
    __syncthreads();
    const float rstd = rsqrtf((sred[0] + sred[1] + sred[2] + sred[3]) *
                              (1.0f / (float)D_HALF) + 1e-5f);

    // --- gamma/beta + exact-erf GELU -> smem lat half ---
    {
        float g[4];
#pragma unroll
        for (int k = 0; k < 4; k++) {
            const int d = 4 * tid + k;
            const float x = fmaf((h[k] - mu) * rstd, __ldg(&gamma[d]), __ldg(&beta[d]));
            g[k] = 0.5f * x * (1.0f + erff(x * 0.70710678118654752440f));
        }
        srow[128 + tid] = make_float4(g[0], g[1], g[2], g[3]);
    }

    // --- pe row (read once per position) -> smem pe half ---
    srow[tid] = __ldg(&pe4[(size_t)pos * 128 + tid]);

    __syncthreads();  // smem row complete

    // --- one thread replays the row to all tokens via async bulk copies ---
    if (tid == 0) {
        // publish generic-proxy smem writes to the async proxy
        asm volatile("fence.proxy.async.shared::cta;" ::: "memory");
        const uint32_t saddr = (uint32_t)__cvta_generic_to_shared(srow);
        int tok = head;
        while (tok >= 0) {
            const int nxt = __ldg(&g_next[tok]);   // L2 hit; overlaps DMA
            char* gdst = (char*)out4 + (size_t)tok * 4096;
            asm volatile(
                "cp.async.bulk.global.shared::cta.bulk_group [%0], [%1], %2;"
                :: "l"(gdst), "r"(saddr), "r"(4096) : "memory");
            tok = nxt;
        }
        asm volatile("cp.async.bulk.commit_group;" ::: "memory");
        // smem must stay valid until DMA reads finish; wait before block exit
        asm volatile("cp.async.bulk.wait_group 0;" ::: "memory");
    }
}

extern "C" void kernel_launch(void* const* d_in, const int* in_sizes, int n_in,
                              void* d_out, int out_size)
{
    const int*   positions = (const int*)  d_in[0];
    const float* pe        = (const float*)d_in[1];
    const float* W1        = (const float*)d_in[2];
    const float* b1        = (const float*)d_in[3];
    const float* ln_gamma  = (const float*)d_in[4];
    const float* ln_beta   = (const float*)d_in[5];
    float* out = (float*)d_out;

    const int ntok = in_sizes[0];  // B*S = 131072

    void* head_ptr = nullptr;
    cudaGetSymbolAddress(&head_ptr, g_head);
    cudaMemsetAsync(head_ptr, 0xFF, NPOS * sizeof(int));  // heads = -1

    build_kernel<<<(ntok + 255) / 256, 256>>>(positions, ntok);

    gather_kernel<<<NPOS, 128>>>((const float4*)pe, W1, b1, ln_gamma, ln_beta,
                                 (float4*)out);
}

// round 10
// speedup vs baseline: 1.4125x; 1.1114x over previous
#include <cuda_runtime.h>
#include <math.h>
#include <stdint.h>

#define D_HALF   512
#define NPOS     8192
#define SPINE_N  10
#define MAX_TOK  131072
#define NCHAIN   4           // independent chains per position (one per warp)

__constant__ int c_spine[SPINE_N] = {0, 2, 4, 12, 36, 104, 304, 888, 2592, 7568};

// Per-position token linked lists, 4 chains each (device globals: no alloc).
__device__ int g_head[NPOS * NCHAIN];   // memset to -1 each call
__device__ int g_next[MAX_TOK];

// Single pass: push each token onto chain (tok & 3) of its position.
__global__ void __launch_bounds__(256) build_kernel(
    const int* __restrict__ positions, int ntok)
{
    const int i = blockIdx.x * blockDim.x + threadIdx.x;
    if (i < ntok) {
        const int pos = positions[i];
        g_next[i] = atomicExch(&g_head[pos * NCHAIN + (i & (NCHAIN - 1))], i);
    }
}

// One block per position: build the 4 KB concat row (pe || GELU(LN(W1·feats)))
// once in shared memory; then each WARP independently walks its own chain and
// streams full rows — 4 concurrent write streams + 4-way parallel chase.
__global__ void __launch_bounds__(128) gather_kernel(
    const float4* __restrict__ pe4,    // [NPOS, 128] float4
    const float*  __restrict__ W1,     // [512, 3] row-major
    const float*  __restrict__ b1,
    const float*  __restrict__ gamma,
    const float*  __restrict__ beta,
    float4*       __restrict__ out4)   // [ntok, 256] float4
{
    __shared__ alignas(128) float4 srow[256];  // 4 KB: [0,128)=pe, [128,256)=lat
    __shared__ float sred[4];
    __shared__ int   sheads[NCHAIN];

    const int pos  = blockIdx.x;
    const int tid  = threadIdx.x;      // 128 threads, dims 4*tid..4*tid+3
    const int wid  = tid >> 5;
    const int lane = tid & 31;

    if (tid < NCHAIN) sheads[tid] = g_head[pos * NCHAIN + tid];

    // --- lattice features (scalar, per block) ---
    int level = 0;
#pragma unroll
    for (int i = 0; i < SPINE_N; i++) level += (c_spine[i] <= pos) ? 1 : 0;
    const float left  = (float)(pos - c_spine[level - 1]);
    const float right = (level < SPINE_N) ? (float)(c_spine[level] - pos) : 0.0f;
    const float lv    = (float)level;

    // --- h = feats @ W1^T + b1, dims 4*tid..4*tid+3 ---
    float h[4];
    float lsum = 0.0f;
#pragma unroll
    for (int k = 0; k < 4; k++) {
        const int d = 4 * tid + k;
        h[k] = fmaf(__ldg(&W1[d * 3 + 0]), left,
               fmaf(__ldg(&W1[d * 3 + 1]), right,
               fmaf(__ldg(&W1[d * 3 + 2]), lv, __ldg(&b1[d]))));
        lsum += h[k];
    }

    // --- block LayerNorm (mean, then two-pass variance) ---
#pragma unroll
    for (int o = 16; o > 0; o >>= 1) lsum += __shfl_xor_sync(0xffffffffu, lsum, o);
    if ((tid & 31) == 0) sred[tid >> 5] = lsum;
    __syncthreads();

    // early-out if no tokens carry this position (sheads visible after sync)
    const int hmax = max(max(sheads[0], sheads[1]), max(sheads[2], sheads[3]));
    if (hmax < 0) return;

    const float mu = (sred[0] + sred[1] + sred[2] + sred[3]) * (1.0f / (float)D_HALF);

    float vs = 0.0f;
#pragma unroll
    for (int k = 0; k < 4; k++) { const float dd = h[k] - mu; vs = fmaf(dd, dd, vs); }
    __syncthreads();
#pragma unroll
    for (int o = 16; o > 0; o >>= 1) vs += __shfl_xor_sync(0xffffffffu, vs, o);
    if ((tid & 31) == 0) sred[tid >> 5] = vs;
    __syncthreads();
    const float rstd = rsqrtf((sred[0] + sred[1] + sred[2] + sred[3]) *
                              (1.0f / (float)D_HALF) + 1e-5f);

    // --- gamma/beta + exact-erf GELU -> smem lat half ---
    {
        float g[4];
#pragma unroll
        for (int k = 0; k < 4; k++) {
            const int d = 4 * tid + k;
            const float x = fmaf((h[k] - mu) * rstd, __ldg(&gamma[d]), __ldg(&beta[d]));
            g[k] = 0.5f * x * (1.0f + erff(x * 0.70710678118654752440f));
        }
        srow[128 + tid] = make_float4(g[0], g[1], g[2], g[3]);
    }

    // --- pe row (read once per position) -> smem pe half ---
    srow[tid] = __ldg(&pe4[(size_t)pos * 128 + tid]);

    __syncthreads();  // smem row complete

    // --- each warp walks its own chain, streaming full 4 KB rows ---
    // Lane l covers row elements l, l+32, ..., l+224 (8 x float4 = 128 B).
    float4 v[8];
#pragma unroll
    for (int k = 0; k < 8; k++) v[k] = srow[lane + 32 * k];

    int tok = sheads[wid];
    while (tok >= 0) {
        const int nxt = __ldg(&g_next[tok]);   // L2 hit; overlaps stores below
        float4* __restrict__ dst = out4 + (size_t)tok * 256;
#pragma unroll
        for (int k = 0; k < 8; k++) __stcs(dst + lane + 32 * k, v[k]);
        tok = nxt;
    }
}

extern "C" void kernel_launch(void* const* d_in, const int* in_sizes, int n_in,
                              void* d_out, int out_size)
{
    const int*   positions = (const int*)  d_in[0];
    const float* pe        = (const float*)d_in[1];
    const float* W1        = (const float*)d_in[2];
    const float* b1        = (const float*)d_in[3];
    const float* ln_gamma  = (const float*)d_in[4];
    const float* ln_beta   = (const float*)d_in[5];
    float* out = (float*)d_out;

    const int ntok = in_sizes[0];  // B*S = 131072

    void* head_ptr = nullptr;
    cudaGetSymbolAddress(&head_ptr, g_head);
    cudaMemsetAsync(head_ptr, 0xFF, NPOS * NCHAIN * sizeof(int));  // heads = -1

    build_kernel<<<(ntok + 255) / 256, 256>>>(positions, ntok);

    gather_kernel<<<NPOS, 128>>>((const float4*)pe, W1, b1, ln_gamma, ln_beta,
                                 (float4*)out);
}